// round 13
// baseline (speedup 1.0000x reference)
#include <cuda_runtime.h>
#include <cuda_fp16.h>
#include <cstdint>

// Problem constants
#define Bb  2
#define Tt  2048
#define Ee  1024
#define Hh  8
#define Dd  512
#define HDc 4096          // H*D
#define Mc  4096          // B*T
#define Dh  256           // D/2

// fp16 scratch (static device allocations)
__device__ __align__(1024) __half g_xh[(size_t)Mc * Ee];
__device__ __align__(1024) __half g_wqkh[(size_t)2 * HDc * Ee];   // [Wq | Wk]
__device__ __align__(1024) __half g_wvh[(size_t)HDc * Ee];
__device__ __align__(1024) __half g_woh[(size_t)Ee * HDc];
__device__ __align__(1024) __half g_qkh[(size_t)2 * Mc * HDc];    // [q | k]
__device__ __align__(1024) __half g_vTh[(size_t)HDc * Mc];        // [h*D, b*T]
__device__ __align__(1024) __half g_attnh[(size_t)Mc * HDc];
__device__ __align__(1024) __half g_sh[(size_t)Bb * Hh * Tt * Tt];   // 128 MiB
__device__ float g_cos[Tt * Dh];
__device__ float g_sin[Tt * Dh];

// ---------------------------------------------------------------------------
// PTX helpers
// ---------------------------------------------------------------------------
__device__ __forceinline__ uint32_t smem_u32(const void* p) {
    uint32_t a;
    asm("{ .reg .u64 t; cvta.to.shared.u64 t, %1; cvt.u32.u64 %0, t; }" : "=r"(a) : "l"(p));
    return a;
}
__device__ __forceinline__ void cpasync16(uint32_t dst, const void* src) {
    asm volatile("cp.async.cg.shared.global [%0], [%1], 16;" :: "r"(dst), "l"(src));
}
#define CP_COMMIT() asm volatile("cp.async.commit_group;" ::: "memory")
#define CP_WAIT1()  asm volatile("cp.async.wait_group 1;" ::: "memory")

__device__ __forceinline__ void ldsm4(uint32_t& r0, uint32_t& r1, uint32_t& r2, uint32_t& r3,
                                      uint32_t addr) {
    asm volatile("ldmatrix.sync.aligned.m8n8.x4.shared.b16 {%0,%1,%2,%3}, [%4];"
                 : "=r"(r0), "=r"(r1), "=r"(r2), "=r"(r3) : "r"(addr));
}
__device__ __forceinline__ void mma168(float (&c)[4], const uint32_t (&a)[4], const uint32_t (&b)[2]) {
    asm volatile(
        "mma.sync.aligned.m16n8k16.row.col.f32.f16.f16.f32 "
        "{%0,%1,%2,%3}, {%4,%5,%6,%7}, {%8,%9}, {%0,%1,%2,%3};\n"
        : "+f"(c[0]), "+f"(c[1]), "+f"(c[2]), "+f"(c[3])
        : "r"(a[0]), "r"(a[1]), "r"(a[2]), "r"(a[3]), "r"(b[0]), "r"(b[1]));
}

// Swizzled smem offset for (row, 16B-chunk), 128B rows, full 8-way XOR.
__device__ __forceinline__ uint32_t swz(int r, int c) {
    return (uint32_t)(r * 128 + ((c ^ (r & 7)) << 4));
}

// ---------------------------------------------------------------------------
// fp16 tensor-core GEMM:  C = alpha * A[M,K] * B[N,K]^T   (both K-major, NT)
// CSKIP: skip tiles strictly above causal diagonal.  CK: limit K to m0+128.
// OUT16: store C as fp16 (else fp32).  REV: heavy tiles first.
// CTA tile 128x128, K-chunk 64, 128 threads, 4 warps (2m x 2n), warp 64x64,
// 3-stage cp.async pipeline, fragment double-buffer across kk steps,
// one sync per chunk, 2 CTAs/SM.
// ---------------------------------------------------------------------------
#define NSTG   3
#define STG_B  32768                        // A 128*128B + B 128*128B
#define GEMM_SMEM (NSTG * STG_B)            // 98304 -> 2 CTAs/SM (192KB)

template <bool CSKIP, bool CK, bool OUT16, bool REV>
__global__ __launch_bounds__(128, 2) void gemm_fp16(
    const __half* __restrict__ Ag, const __half* __restrict__ Bg, void* __restrict__ Cg,
    int Kdim, int lda, int ldb, int ldc,
    long long aO, long long aI, long long bO, long long bI, long long cO, long long cI,
    float alpha)
{
    const int my = REV ? (gridDim.y - 1 - blockIdx.y) : blockIdx.y;
    const int m0 = my * 128;
    const int n0 = blockIdx.x * 128;
    if (CSKIP && n0 >= m0 + 128) return;

    const int z = blockIdx.z;
    const __half* A = Ag + (long long)(z >> 3) * aO + (long long)(z & 7) * aI;
    const __half* B = Bg + (long long)(z >> 3) * bO + (long long)(z & 7) * bI;

    const int kLim = CK ? ((Kdim < m0 + 128) ? Kdim : (m0 + 128)) : Kdim;
    const int nk = kLim >> 6;               // 64-wide K chunks

    extern __shared__ char smem[];
    const uint32_t sb = smem_u32(smem);
    const int tid = threadIdx.x, wid = tid >> 5, lane = tid & 31;
    const int wm = wid & 1, wn = wid >> 1;   // 2m x 2n warp grid

    const int ldr = tid >> 3;                // row group 0..15 (x8 -> 128 rows)
    const int ldc8 = tid & 7;                // 16B chunk 0..7 within 128B row
    auto load_stage = [&](int kt) {
        uint32_t stA = sb + (kt % NSTG) * STG_B;
        uint32_t stB = stA + 16384;
        const __half* Asrc = A + (size_t)m0 * lda + kt * 64;
        const __half* Bsrc = B + (size_t)n0 * ldb + kt * 64;
#pragma unroll
        for (int p = 0; p < 8; p++) {
            int r = ldr + p * 16;
            cpasync16(stA + swz(r, ldc8), Asrc + (size_t)r * lda + ldc8 * 8);
        }
#pragma unroll
        for (int p = 0; p < 8; p++) {
            int r = ldr + p * 16;
            cpasync16(stB + swz(r, ldc8), Bsrc + (size_t)r * ldb + ldc8 * 8);
        }
    };

#pragma unroll
    for (int s = 0; s < NSTG - 1; s++) { if (s < nk) load_stage(s); CP_COMMIT(); }

    float acc[4][8][4] = {};

    const int lrow = lane & 15;
    const int chHalf = lane >> 4;

    uint32_t a[2][4][4], b[2][8][2];

    // fragment fetch for k-slice kk of the chunk at (stA, stB) into buffer bf
    auto ldfrag = [&](int bf, uint32_t stA, uint32_t stB, int kk) {
        const int ch = kk * 2 + chHalf;
#pragma unroll
        for (int i = 0; i < 4; i++) {
            int r = wm * 64 + i * 16 + lrow;
            ldsm4(a[bf][i][0], a[bf][i][1], a[bf][i][2], a[bf][i][3], stA + swz(r, ch));
        }
#pragma unroll
        for (int jp = 0; jp < 4; jp++) {
            int r = wn * 64 + jp * 16 + lrow;
            uint32_t t0, t1, t2, t3;
            ldsm4(t0, t1, t2, t3, stB + swz(r, ch));
            b[bf][jp * 2][0] = t0; b[bf][jp * 2 + 1][0] = t1;
            b[bf][jp * 2][1] = t2; b[bf][jp * 2 + 1][1] = t3;
        }
    };

    for (int kt = 0; kt < nk; kt++) {
        CP_WAIT1();
        __syncthreads();
        uint32_t stA = sb + (kt % NSTG) * STG_B;
        uint32_t stB = stA + 16384;

        ldfrag(0, stA, stB, 0);              // first fragments before cp burst
        if (kt + NSTG - 1 < nk) load_stage(kt + NSTG - 1);
        CP_COMMIT();

#pragma unroll
        for (int kk = 0; kk < 4; kk++) {
            const int cur = kk & 1;
            if (kk < 3) ldfrag(cur ^ 1, stA, stB, kk + 1);
#pragma unroll
            for (int i = 0; i < 4; i++)
#pragma unroll
                for (int j = 0; j < 8; j++) mma168(acc[i][j], a[cur][i], b[cur][j]);
        }
    }

    const int er = lane >> 2, ec = (lane & 3) * 2;
    if (OUT16) {
        __half* C = (__half*)Cg + (long long)(z >> 3) * cO + (long long)(z & 7) * cI;
#pragma unroll
        for (int i = 0; i < 4; i++) {
            int r0 = m0 + wm * 64 + i * 16 + er;
#pragma unroll
            for (int j = 0; j < 8; j++) {
                int c0 = n0 + wn * 64 + j * 8 + ec;
                __half2 h01 = __floats2half2_rn(acc[i][j][0] * alpha, acc[i][j][1] * alpha);
                __half2 h23 = __floats2half2_rn(acc[i][j][2] * alpha, acc[i][j][3] * alpha);
                *(__half2*)(C + (size_t)r0 * ldc + c0) = h01;
                *(__half2*)(C + (size_t)(r0 + 8) * ldc + c0) = h23;
            }
        }
    } else {
        float* C = (float*)Cg + (long long)(z >> 3) * cO + (long long)(z & 7) * cI;
#pragma unroll
        for (int i = 0; i < 4; i++) {
            int r0 = m0 + wm * 64 + i * 16 + er;
#pragma unroll
            for (int j = 0; j < 8; j++) {
                int c0 = n0 + wn * 64 + j * 8 + ec;
                *(float2*)(C + (size_t)r0 * ldc + c0) =
                    make_float2(acc[i][j][0] * alpha, acc[i][j][1] * alpha);
                *(float2*)(C + (size_t)(r0 + 8) * ldc + c0) =
                    make_float2(acc[i][j][2] * alpha, acc[i][j][3] * alpha);
            }
        }
    }
}

// ---------------------------------------------------------------------------
// fused fp32 -> fp16 conversion for all 5 input tensors, 4 float4 per thread
// ---------------------------------------------------------------------------
__global__ void f2h5(const float4* __restrict__ s0, const float4* __restrict__ s1,
                     const float4* __restrict__ s2, const float4* __restrict__ s3,
                     const float4* __restrict__ s4,
                     uint2* __restrict__ d0, uint2* __restrict__ d1,
                     uint2* __restrict__ d2, uint2* __restrict__ d3,
                     uint2* __restrict__ d4) {
    int which = blockIdx.x >> 10;            // 1024 blocks per tensor
    int base = (blockIdx.x & 1023) * 1024 + threadIdx.x;
    const float4* src = which == 0 ? s0 : which == 1 ? s1 : which == 2 ? s2
                      : which == 3 ? s3 : s4;
    uint2* dst = which == 0 ? d0 : which == 1 ? d1 : which == 2 ? d2
               : which == 3 ? d3 : d4;
    float4 v[4];
#pragma unroll
    for (int p = 0; p < 4; p++) v[p] = src[base + p * 256];
#pragma unroll
    for (int p = 0; p < 4; p++) {
        __half2 a = __floats2half2_rn(v[p].x, v[p].y);
        __half2 b = __floats2half2_rn(v[p].z, v[p].w);
        dst[base + p * 256] = make_uint2(*(uint32_t*)&a, *(uint32_t*)&b);
    }
}

// ---------------------------------------------------------------------------
// RoPE (fast-math-immune)
// ---------------------------------------------------------------------------
__device__ __forceinline__ void sincos_cw(float a, float* sp, float* cp) {
    float j = rintf(a * 0.63661977236758138f);
    int   q = (int)j;
    float r = fmaf(j, -1.5707962512969971e+00f, a);
    r = fmaf(j, -7.5497894158615964e-08f, r);
    r = fmaf(j, -5.3903029534742385e-15f, r);
    float x2 = r * r;
    float s = r * (1.f + x2 * (-1.6666667e-1f + x2 * (8.3333333e-3f +
                    x2 * (-1.9841270e-4f + x2 * 2.7557319e-6f))));
    float c = 1.f + x2 * (-0.5f + x2 * (4.1666667e-2f +
                    x2 * (-1.3888889e-3f + x2 * 2.4801587e-5f)));
    switch (q & 3) {
        case 0: *sp =  s; *cp =  c; break;
        case 1: *sp =  c; *cp = -s; break;
        case 2: *sp = -s; *cp = -c; break;
        default:*sp = -c; *cp =  s; break;
    }
}

__global__ void rope_table() {
    int idx = blockIdx.x * 256 + threadIdx.x;
    int d = idx & 255, t = idx >> 8;
    float e = (float)d * (1.0f / 256.0f);
    const float LH = 13.287712097167969f;
    const float LL = 2.8238148e-7f;
    float p = -fmaf(e, LH, e * LL);
    float nf = floorf(p);
    float f  = p - nf;
    float y  = f * 0.69314718055994531f;
    float er = 1.f + y * (1.f + y * (0.5f + y * (0.16666667f + y * (0.041666667f +
               y * (0.0083333333f + y * (0.0013888889f + y * (1.9841270e-4f +
               y * (2.4801587e-5f + y * 2.7557319e-6f))))))));
    float invf = er * __int_as_float(((int)nf + 127) << 23);
    float ang = (float)t * invf;
    float s, c;
    sincos_cw(ang, &s, &c);
    g_cos[idx] = c;
    g_sin[idx] = s;
}

// In-place RoPE on fp16 q and k halves of g_qkh; 2 freq-pairs per thread.
__global__ void rope_apply() {
    int idx = blockIdx.x * 256 + threadIdx.x;   // B*T*H*128 threads
    int dp = idx & 127;
    int h = (idx >> 7) & 7;
    int t = (idx >> 10) & 2047;
    int b = idx >> 21;
    float2 cs0 = *(const float2*)&g_cos[t * 256 + dp * 2];
    float2 sn0 = *(const float2*)&g_sin[t * 256 + dp * 2];
    size_t base = ((size_t)(b * Tt + t)) * HDc + h * Dd + dp * 2;
    const size_t KOFF = (size_t)Mc * HDc;
#pragma unroll
    for (int w = 0; w < 2; w++) {
        __half* g = (__half*)g_qkh + w * KOFF;
        float2 x1 = __half22float2(*(__half2*)(g + base));
        float2 x2 = __half22float2(*(__half2*)(g + base + 256));
        __half2 o1 = __floats2half2_rn(x1.x * cs0.x - x2.x * sn0.x,
                                       x1.y * cs0.y - x2.y * sn0.y);
        __half2 o2 = __floats2half2_rn(x1.x * sn0.x + x2.x * cs0.x,
                                       x1.y * sn0.y + x2.y * cs0.y);
        *(__half2*)(g + base) = o1;
        *(__half2*)(g + base + 256) = o2;
    }
}

// ---------------------------------------------------------------------------
// Causal softmax on fp16 S; loads/stores only up to row's 128 pad boundary.
// ---------------------------------------------------------------------------
__global__ void softmax_causal(__half2* __restrict__ S) {
    long long rr = blockIdx.x;
    long long zz = rr >> 11;
    int i = (int)(rr & 2047);
    __half2* row = S + zz * (Tt * Tt / 2) + (size_t)i * (Tt / 2);
    const int L = i + 1;
    const int Lpad = (L + 127) & ~127;
    const int tid = threadIdx.x;
    __shared__ float red[256];

    float v[8];
    float mx = -3.4e38f;
#pragma unroll
    for (int p = 0; p < 4; p++) {
        int j2 = tid + p * 256;
        if (2 * j2 < Lpad) {
            float2 f = __half22float2(row[j2]);
            v[p * 2]     = (2 * j2     < L) ? f.x : -3.4e38f;
            v[p * 2 + 1] = (2 * j2 + 1 < L) ? f.y : -3.4e38f;
        } else {
            v[p * 2] = -3.4e38f; v[p * 2 + 1] = -3.4e38f;
        }
        mx = fmaxf(mx, fmaxf(v[p * 2], v[p * 2 + 1]));
    }
    red[tid] = mx; __syncthreads();
    for (int s = 128; s > 0; s >>= 1) {
        if (tid < s) red[tid] = fmaxf(red[tid], red[tid + s]);
        __syncthreads();
    }
    mx = red[0]; __syncthreads();

    float sum = 0.f;
#pragma unroll
    for (int p = 0; p < 8; p++) {
        float e = (v[p] > -1e38f) ? expf(v[p] - mx) : 0.f;
        v[p] = e;
        sum += e;
    }
    red[tid] = sum; __syncthreads();
    for (int s = 128; s > 0; s >>= 1) {
        if (tid < s) red[tid] += red[tid + s];
        __syncthreads();
    }
    float inv = 1.0f / red[0];

#pragma unroll
    for (int p = 0; p < 4; p++) {
        int j2 = tid + p * 256;
        if (2 * j2 < Lpad)
            row[j2] = __floats2half2_rn(v[p * 2] * inv, v[p * 2 + 1] * inv);
    }
}

// ---------------------------------------------------------------------------
extern "C" void kernel_launch(void* const* d_in, const int* in_sizes, int n_in,
                              void* d_out, int out_size) {
    const float* x  = (const float*)d_in[0];
    const float* Wq = (const float*)d_in[1];
    const float* Wk = (const float*)d_in[2];
    const float* Wv = (const float*)d_in[3];
    const float* Wo = (const float*)d_in[4];
    float* out = (float*)d_out;

    __half *xh, *wqkh, *wvh, *woh, *qkh, *vTh, *attnh, *sh;
    cudaGetSymbolAddress((void**)&xh, g_xh);
    cudaGetSymbolAddress((void**)&wqkh, g_wqkh);
    cudaGetSymbolAddress((void**)&wvh, g_wvh);
    cudaGetSymbolAddress((void**)&woh, g_woh);
    cudaGetSymbolAddress((void**)&qkh, g_qkh);
    cudaGetSymbolAddress((void**)&vTh, g_vTh);
    cudaGetSymbolAddress((void**)&attnh, g_attnh);
    cudaGetSymbolAddress((void**)&sh, g_sh);

    cudaFuncSetAttribute(gemm_fp16<false, false, true, false>,
                         cudaFuncAttributeMaxDynamicSharedMemorySize, GEMM_SMEM);
    cudaFuncSetAttribute(gemm_fp16<false, false, true, false>,
                         cudaFuncAttributePreferredSharedMemoryCarveout, 100);
    cudaFuncSetAttribute(gemm_fp16<true, false, true, false>,
                         cudaFuncAttributeMaxDynamicSharedMemorySize, GEMM_SMEM);
    cudaFuncSetAttribute(gemm_fp16<true, false, true, false>,
                         cudaFuncAttributePreferredSharedMemoryCarveout, 100);
    cudaFuncSetAttribute(gemm_fp16<false, true, true, true>,
                         cudaFuncAttributeMaxDynamicSharedMemorySize, GEMM_SMEM);
    cudaFuncSetAttribute(gemm_fp16<false, true, true, true>,
                         cudaFuncAttributePreferredSharedMemoryCarveout, 100);
    cudaFuncSetAttribute(gemm_fp16<false, false, false, false>,
                         cudaFuncAttributeMaxDynamicSharedMemorySize, GEMM_SMEM);
    cudaFuncSetAttribute(gemm_fp16<false, false, false, false>,
                         cudaFuncAttributePreferredSharedMemoryCarveout, 100);

    dim3 blk(128);
    const long long TT  = (long long)Tt * Tt;
    const long long THD = (long long)Tt * HDc;
    const long long WSZ = (long long)HDc * Ee;     // one weight tensor
    const long long QSZ = (long long)Mc * HDc;     // one activation tensor

    // 0) convert raw fp32 inputs to fp16 scratch (single fused launch, 4x ILP)
    f2h5<<<5 * 1024, 256>>>((const float4*)x, (const float4*)Wq, (const float4*)Wk,
                            (const float4*)Wv, (const float4*)Wo,
                            (uint2*)xh, (uint2*)wqkh, (uint2*)(wqkh + WSZ),
                            (uint2*)wvh, (uint2*)woh);

    // 1) Q and K projections fused in one launch (z selects Wq/Wk, q/k)
    gemm_fp16<false, false, true, false><<<dim3(32, 32, 2), blk, GEMM_SMEM>>>(
        xh, wqkh, qkh, Ee, Ee, Ee, HDc,
        0, 0, 0, WSZ, 0, QSZ, 1.f);
    // vT[hd, m] = Wv[hd,:] . x[m,:]
    gemm_fp16<false, false, true, false><<<dim3(32, 32, 1), blk, GEMM_SMEM>>>(
        wvh, xh, vTh, Ee, Ee, Ee, Mc, 0, 0, 0, 0, 0, 0, 1.f);

    // 2) RoPE on q, k
    rope_table<<<(Tt * Dh) / 256, 256>>>();
    rope_apply<<<(Bb * Tt * Hh * 128) / 256, 256>>>();

    // 3) scores[b,h] = scale * q[b,h] @ k[b,h]^T   (causal tile skip)
    gemm_fp16<true, false, true, false><<<dim3(16, 16, Bb * Hh), blk, GEMM_SMEM>>>(
        qkh, qkh + QSZ, sh, Dd, HDc, HDc, Tt,
        THD, (long long)Dd, THD, (long long)Dd,
        (long long)Hh * TT, TT, 0.044194173824159216f);

    // 4) causal softmax (fp16 in/out)
    softmax_causal<<<Bb * Hh * Tt, 256>>>((__half2*)sh);

    // 5) attn[b,h] = P[b,h] @ vT[b,h]^T   (NT, causal K limit, heavy-first)
    gemm_fp16<false, true, true, true><<<dim3(4, 16, Bb * Hh), blk, GEMM_SMEM>>>(
        sh, vTh, attnh, Tt, Tt, Mc, HDc,
        (long long)Hh * TT, TT,
        (long long)Tt, (long long)Dd * Mc,
        (long long)Tt * HDc, (long long)Dd, 1.f);

    // 6) out = attn_flat @ Wo^T  (fp32 output)
    gemm_fp16<false, false, false, false><<<dim3(8, 32, 1), blk, GEMM_SMEM>>>(
        attnh, woh, out, HDc, HDc, HDc, Ee, 0, 0, 0, 0, 0, 0, 1.f);
}

// round 14
// speedup vs baseline: 1.0381x; 1.0381x over previous
#include <cuda_runtime.h>
#include <cuda_fp16.h>
#include <cstdint>

// Problem constants
#define Bb  2
#define Tt  2048
#define Ee  1024
#define Hh  8
#define Dd  512
#define HDc 4096          // H*D
#define Mc  4096          // B*T
#define Dh  256           // D/2

// fp16 scratch (static device allocations)
__device__ __align__(1024) __half g_xh[(size_t)Mc * Ee];
__device__ __align__(1024) __half g_wqkh[(size_t)2 * HDc * Ee];   // [Wq | Wk]
__device__ __align__(1024) __half g_wvh[(size_t)HDc * Ee];
__device__ __align__(1024) __half g_woh[(size_t)Ee * HDc];
__device__ __align__(1024) __half g_qkh[(size_t)2 * Mc * HDc];    // [q | k]
__device__ __align__(1024) __half g_vTh[(size_t)HDc * Mc];        // [h*D, b*T]
__device__ __align__(1024) __half g_attnh[(size_t)Mc * HDc];
__device__ __align__(1024) __half g_sh[(size_t)Bb * Hh * Tt * Tt];   // 128 MiB
__device__ float g_cos[Tt * Dh];
__device__ float g_sin[Tt * Dh];

struct GemmPtrs {
    const __half* A[3];
    const __half* B[3];
    void* C[3];
};

// ---------------------------------------------------------------------------
// PTX helpers
// ---------------------------------------------------------------------------
__device__ __forceinline__ uint32_t smem_u32(const void* p) {
    uint32_t a;
    asm("{ .reg .u64 t; cvta.to.shared.u64 t, %1; cvt.u32.u64 %0, t; }" : "=r"(a) : "l"(p));
    return a;
}
__device__ __forceinline__ void cpasync16(uint32_t dst, const void* src) {
    asm volatile("cp.async.cg.shared.global [%0], [%1], 16;" :: "r"(dst), "l"(src));
}
#define CP_COMMIT() asm volatile("cp.async.commit_group;" ::: "memory")
#define CP_WAIT1()  asm volatile("cp.async.wait_group 1;" ::: "memory")

__device__ __forceinline__ void ldsm4(uint32_t& r0, uint32_t& r1, uint32_t& r2, uint32_t& r3,
                                      uint32_t addr) {
    asm volatile("ldmatrix.sync.aligned.m8n8.x4.shared.b16 {%0,%1,%2,%3}, [%4];"
                 : "=r"(r0), "=r"(r1), "=r"(r2), "=r"(r3) : "r"(addr));
}
__device__ __forceinline__ void mma168(float (&c)[4], const uint32_t (&a)[4], const uint32_t (&b)[2]) {
    asm volatile(
        "mma.sync.aligned.m16n8k16.row.col.f32.f16.f16.f32 "
        "{%0,%1,%2,%3}, {%4,%5,%6,%7}, {%8,%9}, {%0,%1,%2,%3};\n"
        : "+f"(c[0]), "+f"(c[1]), "+f"(c[2]), "+f"(c[3])
        : "r"(a[0]), "r"(a[1]), "r"(a[2]), "r"(a[3]), "r"(b[0]), "r"(b[1]));
}

// Swizzled smem offset for (row, 16B-chunk), 128B rows, full 8-way XOR.
__device__ __forceinline__ uint32_t swz(int r, int c) {
    return (uint32_t)(r * 128 + ((c ^ (r & 7)) << 4));
}

// ---------------------------------------------------------------------------
// fp16 tensor-core GEMM:  C = alpha * A[M,K] * B[N,K]^T   (both K-major, NT)
// CSKIP: skip tiles strictly above causal diagonal.  CK: limit K to m0+128.
// OUT16: store C as fp16 (else fp32).  REV: heavy tiles first.
// PSEL: z indexes the pointer table directly (batched distinct GEMMs);
//       else entry 0 + affine offsets (z>>3)*Outer + (z&7)*Inner.
// CTA tile 128x128, K-chunk 64, 128 threads, 4 warps (2m x 2n), warp 64x64,
// 3-stage cp.async pipeline, one sync per chunk, 2 CTAs/SM.
// ---------------------------------------------------------------------------
#define NSTG   3
#define STG_B  32768                        // A 128*128B + B 128*128B
#define GEMM_SMEM (NSTG * STG_B)            // 98304 -> 2 CTAs/SM (192KB)

template <bool CSKIP, bool CK, bool OUT16, bool REV, bool PSEL>
__global__ __launch_bounds__(128, 2) void gemm_fp16(
    GemmPtrs P, int Kdim, int lda, int ldb, int ldc,
    long long aO, long long aI, long long bO, long long bI, long long cO, long long cI,
    float alpha)
{
    const int my = REV ? (gridDim.y - 1 - blockIdx.y) : blockIdx.y;
    const int m0 = my * 128;
    const int n0 = blockIdx.x * 128;
    if (CSKIP && n0 >= m0 + 128) return;

    const int z = blockIdx.z;
    const __half* A;
    const __half* B;
    if (PSEL) {
        A = P.A[z];
        B = P.B[z];
    } else {
        A = P.A[0] + (long long)(z >> 3) * aO + (long long)(z & 7) * aI;
        B = P.B[0] + (long long)(z >> 3) * bO + (long long)(z & 7) * bI;
    }

    const int kLim = CK ? ((Kdim < m0 + 128) ? Kdim : (m0 + 128)) : Kdim;
    const int nk = kLim >> 6;               // 64-wide K chunks

    extern __shared__ char smem[];
    const uint32_t sb = smem_u32(smem);
    const int tid = threadIdx.x, wid = tid >> 5, lane = tid & 31;
    const int wm = wid & 1, wn = wid >> 1;   // 2m x 2n warp grid

    const int ldr = tid >> 3;                // row group 0..15 (x8 -> 128 rows)
    const int ldc8 = tid & 7;                // 16B chunk 0..7 within 128B row
    auto load_stage = [&](int kt) {
        uint32_t stA = sb + (kt % NSTG) * STG_B;
        uint32_t stB = stA + 16384;
        const __half* Asrc = A + (size_t)m0 * lda + kt * 64;
        const __half* Bsrc = B + (size_t)n0 * ldb + kt * 64;
#pragma unroll
        for (int p = 0; p < 8; p++) {
            int r = ldr + p * 16;
            cpasync16(stA + swz(r, ldc8), Asrc + (size_t)r * lda + ldc8 * 8);
        }
#pragma unroll
        for (int p = 0; p < 8; p++) {
            int r = ldr + p * 16;
            cpasync16(stB + swz(r, ldc8), Bsrc + (size_t)r * ldb + ldc8 * 8);
        }
    };

#pragma unroll
    for (int s = 0; s < NSTG - 1; s++) { if (s < nk) load_stage(s); CP_COMMIT(); }

    float acc[4][8][4] = {};

    const int lrow = lane & 15;
    const int chHalf = lane >> 4;

    for (int kt = 0; kt < nk; kt++) {
        CP_WAIT1();
        __syncthreads();
        if (kt + NSTG - 1 < nk) load_stage(kt + NSTG - 1);
        CP_COMMIT();

        uint32_t stA = sb + (kt % NSTG) * STG_B;
        uint32_t stB = stA + 16384;
#pragma unroll
        for (int kk = 0; kk < 4; kk++) {
            const int ch = kk * 2 + chHalf;
            uint32_t a[4][4], b[8][2];
#pragma unroll
            for (int i = 0; i < 4; i++) {
                int r = wm * 64 + i * 16 + lrow;
                ldsm4(a[i][0], a[i][1], a[i][2], a[i][3], stA + swz(r, ch));
            }
#pragma unroll
            for (int jp = 0; jp < 4; jp++) {
                int r = wn * 64 + jp * 16 + lrow;
                uint32_t t0, t1, t2, t3;
                ldsm4(t0, t1, t2, t3, stB + swz(r, ch));
                b[jp * 2][0] = t0; b[jp * 2 + 1][0] = t1;
                b[jp * 2][1] = t2; b[jp * 2 + 1][1] = t3;
            }
#pragma unroll
            for (int i = 0; i < 4; i++)
#pragma unroll
                for (int j = 0; j < 8; j++) mma168(acc[i][j], a[i], b[j]);
        }
    }

    const int er = lane >> 2, ec = (lane & 3) * 2;
    if (OUT16) {
        __half* C = PSEL ? (__half*)P.C[z]
                  : (__half*)P.C[0] + (long long)(z >> 3) * cO + (long long)(z & 7) * cI;
#pragma unroll
        for (int i = 0; i < 4; i++) {
            int r0 = m0 + wm * 64 + i * 16 + er;
#pragma unroll
            for (int j = 0; j < 8; j++) {
                int c0 = n0 + wn * 64 + j * 8 + ec;
                __half2 h01 = __floats2half2_rn(acc[i][j][0] * alpha, acc[i][j][1] * alpha);
                __half2 h23 = __floats2half2_rn(acc[i][j][2] * alpha, acc[i][j][3] * alpha);
                *(__half2*)(C + (size_t)r0 * ldc + c0) = h01;
                *(__half2*)(C + (size_t)(r0 + 8) * ldc + c0) = h23;
            }
        }
    } else {
        float* C = PSEL ? (float*)P.C[z]
                 : (float*)P.C[0] + (long long)(z >> 3) * cO + (long long)(z & 7) * cI;
#pragma unroll
        for (int i = 0; i < 4; i++) {
            int r0 = m0 + wm * 64 + i * 16 + er;
#pragma unroll
            for (int j = 0; j < 8; j++) {
                int c0 = n0 + wn * 64 + j * 8 + ec;
                *(float2*)(C + (size_t)r0 * ldc + c0) =
                    make_float2(acc[i][j][0] * alpha, acc[i][j][1] * alpha);
                *(float2*)(C + (size_t)(r0 + 8) * ldc + c0) =
                    make_float2(acc[i][j][2] * alpha, acc[i][j][3] * alpha);
            }
        }
    }
}

// ---------------------------------------------------------------------------
// fused fp32 -> fp16 conversion for all 5 input tensors, 4 float4 per thread
// ---------------------------------------------------------------------------
__global__ void f2h5(const float4* __restrict__ s0, const float4* __restrict__ s1,
                     const float4* __restrict__ s2, const float4* __restrict__ s3,
                     const float4* __restrict__ s4,
                     uint2* __restrict__ d0, uint2* __restrict__ d1,
                     uint2* __restrict__ d2, uint2* __restrict__ d3,
                     uint2* __restrict__ d4) {
    int which = blockIdx.x >> 10;            // 1024 blocks per tensor
    int base = (blockIdx.x & 1023) * 1024 + threadIdx.x;
    const float4* src = which == 0 ? s0 : which == 1 ? s1 : which == 2 ? s2
                      : which == 3 ? s3 : s4;
    uint2* dst = which == 0 ? d0 : which == 1 ? d1 : which == 2 ? d2
               : which == 3 ? d3 : d4;
    float4 v[4];
#pragma unroll
    for (int p = 0; p < 4; p++) v[p] = src[base + p * 256];
#pragma unroll
    for (int p = 0; p < 4; p++) {
        __half2 a = __floats2half2_rn(v[p].x, v[p].y);
        __half2 b = __floats2half2_rn(v[p].z, v[p].w);
        dst[base + p * 256] = make_uint2(*(uint32_t*)&a, *(uint32_t*)&b);
    }
}

// ---------------------------------------------------------------------------
// RoPE (fast-math-immune)
// ---------------------------------------------------------------------------
__device__ __forceinline__ void sincos_cw(float a, float* sp, float* cp) {
    float j = rintf(a * 0.63661977236758138f);
    int   q = (int)j;
    float r = fmaf(j, -1.5707962512969971e+00f, a);
    r = fmaf(j, -7.5497894158615964e-08f, r);
    r = fmaf(j, -5.3903029534742385e-15f, r);
    float x2 = r * r;
    float s = r * (1.f + x2 * (-1.6666667e-1f + x2 * (8.3333333e-3f +
                    x2 * (-1.9841270e-4f + x2 * 2.7557319e-6f))));
    float c = 1.f + x2 * (-0.5f + x2 * (4.1666667e-2f +
                    x2 * (-1.3888889e-3f + x2 * 2.4801587e-5f)));
    switch (q & 3) {
        case 0: *sp =  s; *cp =  c; break;
        case 1: *sp =  c; *cp = -s; break;
        case 2: *sp = -s; *cp = -c; break;
        default:*sp = -c; *cp =  s; break;
    }
}

__global__ void rope_table() {
    int idx = blockIdx.x * 256 + threadIdx.x;
    int d = idx & 255, t = idx >> 8;
    float e = (float)d * (1.0f / 256.0f);
    const float LH = 13.287712097167969f;
    const float LL = 2.8238148e-7f;
    float p = -fmaf(e, LH, e * LL);
    float nf = floorf(p);
    float f  = p - nf;
    float y  = f * 0.69314718055994531f;
    float er = 1.f + y * (1.f + y * (0.5f + y * (0.16666667f + y * (0.041666667f +
               y * (0.0083333333f + y * (0.0013888889f + y * (1.9841270e-4f +
               y * (2.4801587e-5f + y * 2.7557319e-6f))))))));
    float invf = er * __int_as_float(((int)nf + 127) << 23);
    float ang = (float)t * invf;
    float s, c;
    sincos_cw(ang, &s, &c);
    g_cos[idx] = c;
    g_sin[idx] = s;
}

// In-place RoPE on fp16 q and k halves of g_qkh; 2 freq-pairs per thread.
__global__ void rope_apply() {
    int idx = blockIdx.x * 256 + threadIdx.x;   // B*T*H*128 threads
    int dp = idx & 127;
    int h = (idx >> 7) & 7;
    int t = (idx >> 10) & 2047;
    int b = idx >> 21;
    float2 cs0 = *(const float2*)&g_cos[t * 256 + dp * 2];
    float2 sn0 = *(const float2*)&g_sin[t * 256 + dp * 2];
    size_t base = ((size_t)(b * Tt + t)) * HDc + h * Dd + dp * 2;
    const size_t KOFF = (size_t)Mc * HDc;
#pragma unroll
    for (int w = 0; w < 2; w++) {
        __half* g = (__half*)g_qkh + w * KOFF;
        float2 x1 = __half22float2(*(__half2*)(g + base));
        float2 x2 = __half22float2(*(__half2*)(g + base + 256));
        __half2 o1 = __floats2half2_rn(x1.x * cs0.x - x2.x * sn0.x,
                                       x1.y * cs0.y - x2.y * sn0.y);
        __half2 o2 = __floats2half2_rn(x1.x * sn0.x + x2.x * cs0.x,
                                       x1.y * sn0.y + x2.y * cs0.y);
        *(__half2*)(g + base) = o1;
        *(__half2*)(g + base + 256) = o2;
    }
}

// ---------------------------------------------------------------------------
// Causal softmax on fp16 S. Loads/stores only up to the row's 128-pad
// boundary. Warp-shuffle reductions: 2 __syncthreads total.
// ---------------------------------------------------------------------------
__global__ void softmax_causal(__half2* __restrict__ S) {
    long long rr = blockIdx.x;
    long long zz = rr >> 11;
    int i = (int)(rr & 2047);
    __half2* row = S + zz * (Tt * Tt / 2) + (size_t)i * (Tt / 2);
    const int L = i + 1;
    const int Lpad = (L + 127) & ~127;
    const int tid = threadIdx.x;
    const int lane = tid & 31, wid = tid >> 5;
    __shared__ float wredM[8], wredS[8];

    float v[8];
    float mx = -3.4e38f;
#pragma unroll
    for (int p = 0; p < 4; p++) {
        int j2 = tid + p * 256;
        if (2 * j2 < Lpad) {
            float2 f = __half22float2(row[j2]);
            v[p * 2]     = (2 * j2     < L) ? f.x : -3.4e38f;
            v[p * 2 + 1] = (2 * j2 + 1 < L) ? f.y : -3.4e38f;
        } else {
            v[p * 2] = -3.4e38f; v[p * 2 + 1] = -3.4e38f;
        }
        mx = fmaxf(mx, fmaxf(v[p * 2], v[p * 2 + 1]));
    }
#pragma unroll
    for (int o = 16; o; o >>= 1) mx = fmaxf(mx, __shfl_xor_sync(0xffffffffu, mx, o));
    if (lane == 0) wredM[wid] = mx;
    __syncthreads();
    mx = wredM[0];
#pragma unroll
    for (int w = 1; w < 8; w++) mx = fmaxf(mx, wredM[w]);

    float sum = 0.f;
#pragma unroll
    for (int p = 0; p < 8; p++) {
        float e = (v[p] > -1e38f) ? expf(v[p] - mx) : 0.f;
        v[p] = e;
        sum += e;
    }
#pragma unroll
    for (int o = 16; o; o >>= 1) sum += __shfl_xor_sync(0xffffffffu, sum, o);
    if (lane == 0) wredS[wid] = sum;
    __syncthreads();
    sum = 0.f;
#pragma unroll
    for (int w = 0; w < 8; w++) sum += wredS[w];
    float inv = 1.0f / sum;

#pragma unroll
    for (int p = 0; p < 4; p++) {
        int j2 = tid + p * 256;
        if (2 * j2 < Lpad)
            row[j2] = __floats2half2_rn(v[p * 2] * inv, v[p * 2 + 1] * inv);
    }
}

// ---------------------------------------------------------------------------
extern "C" void kernel_launch(void* const* d_in, const int* in_sizes, int n_in,
                              void* d_out, int out_size) {
    const float* x  = (const float*)d_in[0];
    const float* Wq = (const float*)d_in[1];
    const float* Wk = (const float*)d_in[2];
    const float* Wv = (const float*)d_in[3];
    const float* Wo = (const float*)d_in[4];
    float* out = (float*)d_out;

    __half *xh, *wqkh, *wvh, *woh, *qkh, *vTh, *attnh, *sh;
    cudaGetSymbolAddress((void**)&xh, g_xh);
    cudaGetSymbolAddress((void**)&wqkh, g_wqkh);
    cudaGetSymbolAddress((void**)&wvh, g_wvh);
    cudaGetSymbolAddress((void**)&woh, g_woh);
    cudaGetSymbolAddress((void**)&qkh, g_qkh);
    cudaGetSymbolAddress((void**)&vTh, g_vTh);
    cudaGetSymbolAddress((void**)&attnh, g_attnh);
    cudaGetSymbolAddress((void**)&sh, g_sh);

    cudaFuncSetAttribute(gemm_fp16<false, false, true, false, true>,
                         cudaFuncAttributeMaxDynamicSharedMemorySize, GEMM_SMEM);
    cudaFuncSetAttribute(gemm_fp16<false, false, true, false, true>,
                         cudaFuncAttributePreferredSharedMemoryCarveout, 100);
    cudaFuncSetAttribute(gemm_fp16<true, false, true, false, false>,
                         cudaFuncAttributeMaxDynamicSharedMemorySize, GEMM_SMEM);
    cudaFuncSetAttribute(gemm_fp16<true, false, true, false, false>,
                         cudaFuncAttributePreferredSharedMemoryCarveout, 100);
    cudaFuncSetAttribute(gemm_fp16<false, true, true, true, false>,
                         cudaFuncAttributeMaxDynamicSharedMemorySize, GEMM_SMEM);
    cudaFuncSetAttribute(gemm_fp16<false, true, true, true, false>,
                         cudaFuncAttributePreferredSharedMemoryCarveout, 100);
    cudaFuncSetAttribute(gemm_fp16<false, false, false, false, false>,
                         cudaFuncAttributeMaxDynamicSharedMemorySize, GEMM_SMEM);
    cudaFuncSetAttribute(gemm_fp16<false, false, false, false, false>,
                         cudaFuncAttributePreferredSharedMemoryCarveout, 100);

    dim3 blk(128);
    const long long TT  = (long long)Tt * Tt;
    const long long THD = (long long)Tt * HDc;
    const long long WSZ = (long long)HDc * Ee;     // one weight tensor
    const long long QSZ = (long long)Mc * HDc;     // one activation tensor

    // 0) convert raw fp32 inputs to fp16 scratch (single fused launch, 4x ILP)
    f2h5<<<5 * 1024, 256>>>((const float4*)x, (const float4*)Wq, (const float4*)Wk,
                            (const float4*)Wv, (const float4*)Wo,
                            (uint2*)xh, (uint2*)wqkh, (uint2*)(wqkh + WSZ),
                            (uint2*)wvh, (uint2*)woh);

    // 1) Q, K, V projections in ONE launch (z selects operand set):
    //    z=0: q = x @ Wq^T,  z=1: k = x @ Wk^T,  z=2: vT = Wv @ x^T
    //    All are 4096x4096x1024 NT GEMMs with lda=ldb=1024, ldc=4096.
    {
        GemmPtrs P{};
        P.A[0] = xh;   P.B[0] = wqkh;        P.C[0] = qkh;
        P.A[1] = xh;   P.B[1] = wqkh + WSZ;  P.C[1] = qkh + QSZ;
        P.A[2] = wvh;  P.B[2] = xh;          P.C[2] = vTh;
        gemm_fp16<false, false, true, false, true><<<dim3(32, 32, 3), blk, GEMM_SMEM>>>(
            P, Ee, Ee, Ee, HDc, 0, 0, 0, 0, 0, 0, 1.f);
    }

    // 2) RoPE on q, k
    rope_table<<<(Tt * Dh) / 256, 256>>>();
    rope_apply<<<(Bb * Tt * Hh * 128) / 256, 256>>>();

    // 3) scores[b,h] = scale * q[b,h] @ k[b,h]^T   (causal tile skip)
    {
        GemmPtrs P{};
        P.A[0] = qkh; P.B[0] = qkh + QSZ; P.C[0] = sh;
        gemm_fp16<true, false, true, false, false><<<dim3(16, 16, Bb * Hh), blk, GEMM_SMEM>>>(
            P, Dd, HDc, HDc, Tt,
            THD, (long long)Dd, THD, (long long)Dd,
            (long long)Hh * TT, TT, 0.044194173824159216f);
    }

    // 4) causal softmax (fp16 in/out, shfl reductions)
    softmax_causal<<<Bb * Hh * Tt, 256>>>((__half2*)sh);

    // 5) attn[b,h] = P[b,h] @ vT[b,h]^T   (NT, causal K limit, heavy-first)
    {
        GemmPtrs P{};
        P.A[0] = sh; P.B[0] = vTh; P.C[0] = attnh;
        gemm_fp16<false, true, true, true, false><<<dim3(4, 16, Bb * Hh), blk, GEMM_SMEM>>>(
            P, Tt, Tt, Mc, HDc,
            (long long)Hh * TT, TT,
            (long long)Tt, (long long)Dd * Mc,
            (long long)Tt * HDc, (long long)Dd, 1.f);
    }

    // 6) out = attn_flat @ Wo^T  (fp32 output)
    {
        GemmPtrs P{};
        P.A[0] = attnh; P.B[0] = woh; P.C[0] = out;
        gemm_fp16<false, false, false, false, false><<<dim3(8, 32, 1), blk, GEMM_SMEM>>>(
            P, HDc, HDc, HDc, Ee, 0, 0, 0, 0, 0, 0, 1.f);
    }
}

// round 15
// speedup vs baseline: 1.0563x; 1.0175x over previous
#include <cuda_runtime.h>
#include <cuda_fp16.h>
#include <cstdint>

// Problem constants
#define Bb  2
#define Tt  2048
#define Ee  1024
#define Hh  8
#define Dd  512
#define HDc 4096          // H*D
#define Mc  4096          // B*T
#define Dh  256           // D/2

// fp16 scratch (static device allocations)
__device__ __align__(1024) __half g_xh[(size_t)Mc * Ee];
__device__ __align__(1024) __half g_wqkh[(size_t)2 * HDc * Ee];   // [Wq | Wk]
__device__ __align__(1024) __half g_wvh[(size_t)HDc * Ee];
__device__ __align__(1024) __half g_woh[(size_t)Ee * HDc];
__device__ __align__(1024) __half g_qkh[(size_t)2 * Mc * HDc];    // [q | k]
__device__ __align__(1024) __half g_vTh[(size_t)HDc * Mc];        // [h*D, b*T]
__device__ __align__(1024) __half g_attnh[(size_t)Mc * HDc];
__device__ __align__(1024) __half g_sh[(size_t)Bb * Hh * Tt * Tt];   // 128 MiB
__device__ float g_cos[Tt * Dh];
__device__ float g_sin[Tt * Dh];

struct GemmPtrs {
    const __half* A[3];
    const __half* B[3];
    void* C[3];
};

// ---------------------------------------------------------------------------
// PTX helpers
// ---------------------------------------------------------------------------
__device__ __forceinline__ uint32_t smem_u32(const void* p) {
    uint32_t a;
    asm("{ .reg .u64 t; cvta.to.shared.u64 t, %1; cvt.u32.u64 %0, t; }" : "=r"(a) : "l"(p));
    return a;
}
__device__ __forceinline__ void cpasync16(uint32_t dst, const void* src) {
    asm volatile("cp.async.cg.shared.global [%0], [%1], 16;" :: "r"(dst), "l"(src));
}
#define CP_COMMIT() asm volatile("cp.async.commit_group;" ::: "memory")
#define CP_WAIT1()  asm volatile("cp.async.wait_group 1;" ::: "memory")

__device__ __forceinline__ void ldsm4(uint32_t& r0, uint32_t& r1, uint32_t& r2, uint32_t& r3,
                                      uint32_t addr) {
    asm volatile("ldmatrix.sync.aligned.m8n8.x4.shared.b16 {%0,%1,%2,%3}, [%4];"
                 : "=r"(r0), "=r"(r1), "=r"(r2), "=r"(r3) : "r"(addr));
}
__device__ __forceinline__ void mma168(float (&c)[4], const uint32_t (&a)[4], const uint32_t (&b)[2]) {
    asm volatile(
        "mma.sync.aligned.m16n8k16.row.col.f32.f16.f16.f32 "
        "{%0,%1,%2,%3}, {%4,%5,%6,%7}, {%8,%9}, {%0,%1,%2,%3};\n"
        : "+f"(c[0]), "+f"(c[1]), "+f"(c[2]), "+f"(c[3])
        : "r"(a[0]), "r"(a[1]), "r"(a[2]), "r"(a[3]), "r"(b[0]), "r"(b[1]));
}

// Swizzled smem offset for (row, 16B-chunk), 128B rows, full 8-way XOR.
__device__ __forceinline__ uint32_t swz(int r, int c) {
    return (uint32_t)(r * 128 + ((c ^ (r & 7)) << 4));
}

// ---------------------------------------------------------------------------
// fp16 tensor-core GEMM:  C = alpha * A[M,K] * B[N,K]^T   (both K-major, NT)
// TRI:  packed lower-triangular tile grid (blockIdx.x = tri index, grid.y=1)
// CK:   limit K to m0+128.  OUT16: store C as fp16 (else fp32).
// REV:  heavy tiles first.  PSEL: z indexes pointer table directly.
// CTA tile 128x128, K-chunk 64, 128 threads, 4 warps (2m x 2n), warp 64x64,
// 3-stage cp.async pipeline, one sync per chunk, 2 CTAs/SM.
// ---------------------------------------------------------------------------
#define NSTG   3
#define STG_B  32768                        // A 128*128B + B 128*128B
#define GEMM_SMEM (NSTG * STG_B)            // 98304 -> 2 CTAs/SM (192KB)

template <bool TRI, bool CK, bool OUT16, bool REV, bool PSEL>
__global__ __launch_bounds__(128, 2) void gemm_fp16(
    GemmPtrs P, int Kdim, int lda, int ldb, int ldc,
    long long aO, long long aI, long long bO, long long bI, long long cO, long long cI,
    float alpha)
{
    int m0, n0;
    if (TRI) {
        int tt = blockIdx.x;
        int r = (int)((sqrtf(8.0f * (float)tt + 1.0f) - 1.0f) * 0.5f);
        if (r * (r + 1) / 2 > tt) r--;
        if ((r + 1) * (r + 2) / 2 <= tt) r++;
        m0 = r * 128;
        n0 = (tt - r * (r + 1) / 2) * 128;
    } else {
        const int my = REV ? (gridDim.y - 1 - blockIdx.y) : blockIdx.y;
        m0 = my * 128;
        n0 = blockIdx.x * 128;
    }

    const int z = blockIdx.z;
    const __half* A;
    const __half* B;
    if (PSEL) {
        A = P.A[z];
        B = P.B[z];
    } else {
        A = P.A[0] + (long long)(z >> 3) * aO + (long long)(z & 7) * aI;
        B = P.B[0] + (long long)(z >> 3) * bO + (long long)(z & 7) * bI;
    }

    const int kLim = CK ? ((Kdim < m0 + 128) ? Kdim : (m0 + 128)) : Kdim;
    const int nk = kLim >> 6;               // 64-wide K chunks

    extern __shared__ char smem[];
    const uint32_t sb = smem_u32(smem);
    const int tid = threadIdx.x, wid = tid >> 5, lane = tid & 31;
    const int wm = wid & 1, wn = wid >> 1;   // 2m x 2n warp grid

    const int ldr = tid >> 3;                // row group 0..15 (x8 -> 128 rows)
    const int ldc8 = tid & 7;                // 16B chunk 0..7 within 128B row
    auto load_stage = [&](int kt) {
        uint32_t stA = sb + (kt % NSTG) * STG_B;
        uint32_t stB = stA + 16384;
        const __half* Asrc = A + (size_t)m0 * lda + kt * 64;
        const __half* Bsrc = B + (size_t)n0 * ldb + kt * 64;
#pragma unroll
        for (int p = 0; p < 8; p++) {
            int r = ldr + p * 16;
            cpasync16(stA + swz(r, ldc8), Asrc + (size_t)r * lda + ldc8 * 8);
        }
#pragma unroll
        for (int p = 0; p < 8; p++) {
            int r = ldr + p * 16;
            cpasync16(stB + swz(r, ldc8), Bsrc + (size_t)r * ldb + ldc8 * 8);
        }
    };

#pragma unroll
    for (int s = 0; s < NSTG - 1; s++) { if (s < nk) load_stage(s); CP_COMMIT(); }

    float acc[4][8][4] = {};

    const int lrow = lane & 15;
    const int chHalf = lane >> 4;

    for (int kt = 0; kt < nk; kt++) {
        CP_WAIT1();
        __syncthreads();
        if (kt + NSTG - 1 < nk) load_stage(kt + NSTG - 1);
        CP_COMMIT();

        uint32_t stA = sb + (kt % NSTG) * STG_B;
        uint32_t stB = stA + 16384;
#pragma unroll
        for (int kk = 0; kk < 4; kk++) {
            const int ch = kk * 2 + chHalf;
            uint32_t a[4][4], b[8][2];
#pragma unroll
            for (int i = 0; i < 4; i++) {
                int r = wm * 64 + i * 16 + lrow;
                ldsm4(a[i][0], a[i][1], a[i][2], a[i][3], stA + swz(r, ch));
            }
#pragma unroll
            for (int jp = 0; jp < 4; jp++) {
                int r = wn * 64 + jp * 16 + lrow;
                uint32_t t0, t1, t2, t3;
                ldsm4(t0, t1, t2, t3, stB + swz(r, ch));
                b[jp * 2][0] = t0; b[jp * 2 + 1][0] = t1;
                b[jp * 2][1] = t2; b[jp * 2 + 1][1] = t3;
            }
#pragma unroll
            for (int i = 0; i < 4; i++)
#pragma unroll
                for (int j = 0; j < 8; j++) mma168(acc[i][j], a[i], b[j]);
        }
    }

    const int er = lane >> 2, ec = (lane & 3) * 2;
    if (OUT16) {
        __half* C = PSEL ? (__half*)P.C[z]
                  : (__half*)P.C[0] + (long long)(z >> 3) * cO + (long long)(z & 7) * cI;
#pragma unroll
        for (int i = 0; i < 4; i++) {
            int r0 = m0 + wm * 64 + i * 16 + er;
#pragma unroll
            for (int j = 0; j < 8; j++) {
                int c0 = n0 + wn * 64 + j * 8 + ec;
                __half2 h01 = __floats2half2_rn(acc[i][j][0] * alpha, acc[i][j][1] * alpha);
                __half2 h23 = __floats2half2_rn(acc[i][j][2] * alpha, acc[i][j][3] * alpha);
                *(__half2*)(C + (size_t)r0 * ldc + c0) = h01;
                *(__half2*)(C + (size_t)(r0 + 8) * ldc + c0) = h23;
            }
        }
    } else {
        float* C = PSEL ? (float*)P.C[z]
                 : (float*)P.C[0] + (long long)(z >> 3) * cO + (long long)(z & 7) * cI;
#pragma unroll
        for (int i = 0; i < 4; i++) {
            int r0 = m0 + wm * 64 + i * 16 + er;
#pragma unroll
            for (int j = 0; j < 8; j++) {
                int c0 = n0 + wn * 64 + j * 8 + ec;
                *(float2*)(C + (size_t)r0 * ldc + c0) =
                    make_float2(acc[i][j][0] * alpha, acc[i][j][1] * alpha);
                *(float2*)(C + (size_t)(r0 + 8) * ldc + c0) =
                    make_float2(acc[i][j][2] * alpha, acc[i][j][3] * alpha);
            }
        }
    }
}

// ---------------------------------------------------------------------------
// fused fp32 -> fp16 conversion for all 5 input tensors, 4 float4 per thread
// ---------------------------------------------------------------------------
__global__ void f2h5(const float4* __restrict__ s0, const float4* __restrict__ s1,
                     const float4* __restrict__ s2, const float4* __restrict__ s3,
                     const float4* __restrict__ s4,
                     uint2* __restrict__ d0, uint2* __restrict__ d1,
                     uint2* __restrict__ d2, uint2* __restrict__ d3,
                     uint2* __restrict__ d4) {
    int which = blockIdx.x >> 10;            // 1024 blocks per tensor
    int base = (blockIdx.x & 1023) * 1024 + threadIdx.x;
    const float4* src = which == 0 ? s0 : which == 1 ? s1 : which == 2 ? s2
                      : which == 3 ? s3 : s4;
    uint2* dst = which == 0 ? d0 : which == 1 ? d1 : which == 2 ? d2
               : which == 3 ? d3 : d4;
    float4 v[4];
#pragma unroll
    for (int p = 0; p < 4; p++) v[p] = src[base + p * 256];
#pragma unroll
    for (int p = 0; p < 4; p++) {
        __half2 a = __floats2half2_rn(v[p].x, v[p].y);
        __half2 b = __floats2half2_rn(v[p].z, v[p].w);
        dst[base + p * 256] = make_uint2(*(uint32_t*)&a, *(uint32_t*)&b);
    }
}

// ---------------------------------------------------------------------------
// RoPE (fast-math-immune)
// ---------------------------------------------------------------------------
__device__ __forceinline__ void sincos_cw(float a, float* sp, float* cp) {
    float j = rintf(a * 0.63661977236758138f);
    int   q = (int)j;
    float r = fmaf(j, -1.5707962512969971e+00f, a);
    r = fmaf(j, -7.5497894158615964e-08f, r);
    r = fmaf(j, -5.3903029534742385e-15f, r);
    float x2 = r * r;
    float s = r * (1.f + x2 * (-1.6666667e-1f + x2 * (8.3333333e-3f +
                    x2 * (-1.9841270e-4f + x2 * 2.7557319e-6f))));
    float c = 1.f + x2 * (-0.5f + x2 * (4.1666667e-2f +
                    x2 * (-1.3888889e-3f + x2 * 2.4801587e-5f)));
    switch (q & 3) {
        case 0: *sp =  s; *cp =  c; break;
        case 1: *sp =  c; *cp = -s; break;
        case 2: *sp = -s; *cp = -c; break;
        default:*sp = -c; *cp =  s; break;
    }
}

__global__ void rope_table() {
    int idx = blockIdx.x * 256 + threadIdx.x;
    int d = idx & 255, t = idx >> 8;
    float e = (float)d * (1.0f / 256.0f);
    const float LH = 13.287712097167969f;
    const float LL = 2.8238148e-7f;
    float p = -fmaf(e, LH, e * LL);
    float nf = floorf(p);
    float f  = p - nf;
    float y  = f * 0.69314718055994531f;
    float er = 1.f + y * (1.f + y * (0.5f + y * (0.16666667f + y * (0.041666667f +
               y * (0.0083333333f + y * (0.0013888889f + y * (1.9841270e-4f +
               y * (2.4801587e-5f + y * 2.7557319e-6f))))))));
    float invf = er * __int_as_float(((int)nf + 127) << 23);
    float ang = (float)t * invf;
    float s, c;
    sincos_cw(ang, &s, &c);
    g_cos[idx] = c;
    g_sin[idx] = s;
}

// In-place RoPE on fp16 q and k halves of g_qkh; 8 d-values (8 pairs' halves)
// per thread via 16B vector loads, both q and k -> high MLP.
__global__ void rope_apply() {
    int idx = blockIdx.x * 256 + threadIdx.x;   // B*T*H*32 threads
    int dq = idx & 31;                           // 8-d group within Dh=256
    int h = (idx >> 5) & 7;
    int t = (idx >> 8) & 2047;
    int b = idx >> 19;

    const float4* cosv = (const float4*)&g_cos[t * 256 + dq * 8];
    const float4* sinv = (const float4*)&g_sin[t * 256 + dq * 8];
    float4 cA = cosv[0], cB = cosv[1];
    float4 sA = sinv[0], sB = sinv[1];
    float cs[8] = {cA.x, cA.y, cA.z, cA.w, cB.x, cB.y, cB.z, cB.w};
    float sn[8] = {sA.x, sA.y, sA.z, sA.w, sB.x, sB.y, sB.z, sB.w};

    size_t base = ((size_t)(b * Tt + t)) * HDc + h * Dd + dq * 8;
    const size_t KOFF = (size_t)Mc * HDc;
#pragma unroll
    for (int w = 0; w < 2; w++) {
        __half* g = (__half*)g_qkh + w * KOFF;
        float4 loRaw = *(const float4*)(g + base);         // d .. d+7   (x1)
        float4 hiRaw = *(const float4*)(g + base + 256);   // d+256 ..   (x2)
        __half2* lo = (__half2*)&loRaw;
        __half2* hi = (__half2*)&hiRaw;
        float4 oLo, oHi;
        __half2* ol = (__half2*)&oLo;
        __half2* oh = (__half2*)&oHi;
#pragma unroll
        for (int j = 0; j < 4; j++) {
            float2 x1 = __half22float2(lo[j]);
            float2 x2 = __half22float2(hi[j]);
            float c0 = cs[2 * j], c1 = cs[2 * j + 1];
            float s0 = sn[2 * j], s1 = sn[2 * j + 1];
            ol[j] = __floats2half2_rn(x1.x * c0 - x2.x * s0, x1.y * c1 - x2.y * s1);
            oh[j] = __floats2half2_rn(x1.x * s0 + x2.x * c0, x1.y * s1 + x2.y * c1);
        }
        *(float4*)(g + base) = oLo;
        *(float4*)(g + base + 256) = oHi;
    }
}

// ---------------------------------------------------------------------------
// Causal softmax on fp16 S. Two adjacent rows per 256-thread block
// (128 threads per row). Loads/stores only up to row's 128-pad boundary.
// Warp-shuffle reductions; 2 __syncthreads total.
// ---------------------------------------------------------------------------
__global__ void softmax_causal(__half2* __restrict__ S) {
    const int tid = threadIdx.x;
    const int grp = tid >> 7;                    // row group 0/1
    const int ltid = tid & 127;
    const int lane = tid & 31;
    const int wig = (tid >> 5) & 3;              // warp within group

    long long rr = (long long)blockIdx.x * 2 + grp;
    long long zz = rr >> 11;
    int i = (int)(rr & 2047);
    __half2* row = S + zz * (Tt * Tt / 2) + (size_t)i * (Tt / 2);
    const int L = i + 1;
    const int Lpad = (L + 127) & ~127;

    __shared__ float wredM[2][4], wredS[2][4];

    float v[16];
    float mx = -3.4e38f;
#pragma unroll
    for (int p = 0; p < 8; p++) {
        int j2 = ltid + p * 128;
        if (2 * j2 < Lpad) {
            float2 f = __half22float2(row[j2]);
            v[p * 2]     = (2 * j2     < L) ? f.x : -3.4e38f;
            v[p * 2 + 1] = (2 * j2 + 1 < L) ? f.y : -3.4e38f;
        } else {
            v[p * 2] = -3.4e38f; v[p * 2 + 1] = -3.4e38f;
        }
        mx = fmaxf(mx, fmaxf(v[p * 2], v[p * 2 + 1]));
    }
#pragma unroll
    for (int o = 16; o; o >>= 1) mx = fmaxf(mx, __shfl_xor_sync(0xffffffffu, mx, o));
    if (lane == 0) wredM[grp][wig] = mx;
    __syncthreads();
    mx = fmaxf(fmaxf(wredM[grp][0], wredM[grp][1]),
               fmaxf(wredM[grp][2], wredM[grp][3]));

    float sum = 0.f;
#pragma unroll
    for (int p = 0; p < 16; p++) {
        float e = (v[p] > -1e38f) ? expf(v[p] - mx) : 0.f;
        v[p] = e;
        sum += e;
    }
#pragma unroll
    for (int o = 16; o; o >>= 1) sum += __shfl_xor_sync(0xffffffffu, sum, o);
    if (lane == 0) wredS[grp][wig] = sum;
    __syncthreads();
    sum = (wredS[grp][0] + wredS[grp][1]) + (wredS[grp][2] + wredS[grp][3]);
    float inv = 1.0f / sum;

#pragma unroll
    for (int p = 0; p < 8; p++) {
        int j2 = ltid + p * 128;
        if (2 * j2 < Lpad)
            row[j2] = __floats2half2_rn(v[p * 2] * inv, v[p * 2 + 1] * inv);
    }
}

// ---------------------------------------------------------------------------
extern "C" void kernel_launch(void* const* d_in, const int* in_sizes, int n_in,
                              void* d_out, int out_size) {
    const float* x  = (const float*)d_in[0];
    const float* Wq = (const float*)d_in[1];
    const float* Wk = (const float*)d_in[2];
    const float* Wv = (const float*)d_in[3];
    const float* Wo = (const float*)d_in[4];
    float* out = (float*)d_out;

    __half *xh, *wqkh, *wvh, *woh, *qkh, *vTh, *attnh, *sh;
    cudaGetSymbolAddress((void**)&xh, g_xh);
    cudaGetSymbolAddress((void**)&wqkh, g_wqkh);
    cudaGetSymbolAddress((void**)&wvh, g_wvh);
    cudaGetSymbolAddress((void**)&woh, g_woh);
    cudaGetSymbolAddress((void**)&qkh, g_qkh);
    cudaGetSymbolAddress((void**)&vTh, g_vTh);
    cudaGetSymbolAddress((void**)&attnh, g_attnh);
    cudaGetSymbolAddress((void**)&sh, g_sh);

    cudaFuncSetAttribute(gemm_fp16<false, false, true, false, true>,
                         cudaFuncAttributeMaxDynamicSharedMemorySize, GEMM_SMEM);
    cudaFuncSetAttribute(gemm_fp16<false, false, true, false, true>,
                         cudaFuncAttributePreferredSharedMemoryCarveout, 100);
    cudaFuncSetAttribute(gemm_fp16<true, false, true, false, false>,
                         cudaFuncAttributeMaxDynamicSharedMemorySize, GEMM_SMEM);
    cudaFuncSetAttribute(gemm_fp16<true, false, true, false, false>,
                         cudaFuncAttributePreferredSharedMemoryCarveout, 100);
    cudaFuncSetAttribute(gemm_fp16<false, true, true, true, false>,
                         cudaFuncAttributeMaxDynamicSharedMemorySize, GEMM_SMEM);
    cudaFuncSetAttribute(gemm_fp16<false, true, true, true, false>,
                         cudaFuncAttributePreferredSharedMemoryCarveout, 100);
    cudaFuncSetAttribute(gemm_fp16<false, false, false, false, false>,
                         cudaFuncAttributeMaxDynamicSharedMemorySize, GEMM_SMEM);
    cudaFuncSetAttribute(gemm_fp16<false, false, false, false, false>,
                         cudaFuncAttributePreferredSharedMemoryCarveout, 100);

    dim3 blk(128);
    const long long TT  = (long long)Tt * Tt;
    const long long THD = (long long)Tt * HDc;
    const long long WSZ = (long long)HDc * Ee;     // one weight tensor
    const long long QSZ = (long long)Mc * HDc;     // one activation tensor

    // 0) convert raw fp32 inputs to fp16 scratch (single fused launch, 4x ILP)
    f2h5<<<5 * 1024, 256>>>((const float4*)x, (const float4*)Wq, (const float4*)Wk,
                            (const float4*)Wv, (const float4*)Wo,
                            (uint2*)xh, (uint2*)wqkh, (uint2*)(wqkh + WSZ),
                            (uint2*)wvh, (uint2*)woh);

    // 1) Q, K, V projections in ONE launch (z selects operand set)
    {
        GemmPtrs P{};
        P.A[0] = xh;   P.B[0] = wqkh;        P.C[0] = qkh;
        P.A[1] = xh;   P.B[1] = wqkh + WSZ;  P.C[1] = qkh + QSZ;
        P.A[2] = wvh;  P.B[2] = xh;          P.C[2] = vTh;
        gemm_fp16<false, false, true, false, true><<<dim3(32, 32, 3), blk, GEMM_SMEM>>>(
            P, Ee, Ee, Ee, HDc, 0, 0, 0, 0, 0, 0, 1.f);
    }

    // 2) RoPE on q, k
    rope_table<<<(Tt * Dh) / 256, 256>>>();
    rope_apply<<<(Bb * Tt * Hh * 32) / 256, 256>>>();

    // 3) scores[b,h] = scale * q[b,h] @ k[b,h]^T  (packed triangular grid)
    {
        GemmPtrs P{};
        P.A[0] = qkh; P.B[0] = qkh + QSZ; P.C[0] = sh;
        gemm_fp16<true, false, true, false, false><<<dim3(136, 1, Bb * Hh), blk, GEMM_SMEM>>>(
            P, Dd, HDc, HDc, Tt,
            THD, (long long)Dd, THD, (long long)Dd,
            (long long)Hh * TT, TT, 0.044194173824159216f);
    }

    // 4) causal softmax (fp16 in/out, 2 rows per block, shfl reductions)
    softmax_causal<<<Bb * Hh * Tt / 2, 256>>>((__half2*)sh);

    // 5) attn[b,h] = P[b,h] @ vT[b,h]^T   (NT, causal K limit, heavy-first)
    {
        GemmPtrs P{};
        P.A[0] = sh; P.B[0] = vTh; P.C[0] = attnh;
        gemm_fp16<false, true, true, true, false><<<dim3(4, 16, Bb * Hh), blk, GEMM_SMEM>>>(
            P, Tt, Tt, Mc, HDc,
            (long long)Hh * TT, TT,
            (long long)Tt, (long long)Dd * Mc,
            (long long)Tt * HDc, (long long)Dd, 1.f);
    }

    // 6) out = attn_flat @ Wo^T  (fp32 output)
    {
        GemmPtrs P{};
        P.A[0] = attnh; P.B[0] = woh; P.C[0] = out;
        gemm_fp16<false, false, false, false, false><<<dim3(8, 32, 1), blk, GEMM_SMEM>>>(
            P, HDc, HDc, HDc, Ee, 0, 0, 0, 0, 0, 0, 1.f);
    }
}

// round 16
// speedup vs baseline: 1.0565x; 1.0001x over previous
#include <cuda_runtime.h>
#include <cuda_fp16.h>
#include <cstdint>

// Problem constants
#define Bb  2
#define Tt  2048
#define Ee  1024
#define Hh  8
#define Dd  512
#define HDc 4096          // H*D
#define Mc  4096          // B*T
#define Dh  256           // D/2

// fp16 scratch (static device allocations)
__device__ __align__(1024) __half g_xh[(size_t)Mc * Ee];
__device__ __align__(1024) __half g_wqkh[(size_t)2 * HDc * Ee];   // [Wq' | Wk'] (rope-paired rows)
__device__ __align__(1024) __half g_wvh[(size_t)HDc * Ee];
__device__ __align__(1024) __half g_woh[(size_t)Ee * HDc];
__device__ __align__(1024) __half g_qkh[(size_t)2 * Mc * HDc];    // [q | k]  (rope-paired features)
__device__ __align__(1024) __half g_vTh[(size_t)HDc * Mc];        // [h*D, b*T]
__device__ __align__(1024) __half g_attnh[(size_t)Mc * HDc];
__device__ __align__(1024) __half g_sh[(size_t)Bb * Hh * Tt * Tt];   // 128 MiB
__device__ float g_cos[Tt * Dh];
__device__ float g_sin[Tt * Dh];

struct GemmPtrs {
    const __half* A[3];
    const __half* B[3];
    void* C[3];
};

// ---------------------------------------------------------------------------
// PTX helpers
// ---------------------------------------------------------------------------
__device__ __forceinline__ uint32_t smem_u32(const void* p) {
    uint32_t a;
    asm("{ .reg .u64 t; cvta.to.shared.u64 t, %1; cvt.u32.u64 %0, t; }" : "=r"(a) : "l"(p));
    return a;
}
__device__ __forceinline__ void cpasync16(uint32_t dst, const void* src) {
    asm volatile("cp.async.cg.shared.global [%0], [%1], 16;" :: "r"(dst), "l"(src));
}
#define CP_COMMIT() asm volatile("cp.async.commit_group;" ::: "memory")
#define CP_WAIT1()  asm volatile("cp.async.wait_group 1;" ::: "memory")

__device__ __forceinline__ void ldsm4(uint32_t& r0, uint32_t& r1, uint32_t& r2, uint32_t& r3,
                                      uint32_t addr) {
    asm volatile("ldmatrix.sync.aligned.m8n8.x4.shared.b16 {%0,%1,%2,%3}, [%4];"
                 : "=r"(r0), "=r"(r1), "=r"(r2), "=r"(r3) : "r"(addr));
}
__device__ __forceinline__ void mma168(float (&c)[4], const uint32_t (&a)[4], const uint32_t (&b)[2]) {
    asm volatile(
        "mma.sync.aligned.m16n8k16.row.col.f32.f16.f16.f32 "
        "{%0,%1,%2,%3}, {%4,%5,%6,%7}, {%8,%9}, {%0,%1,%2,%3};\n"
        : "+f"(c[0]), "+f"(c[1]), "+f"(c[2]), "+f"(c[3])
        : "r"(a[0]), "r"(a[1]), "r"(a[2]), "r"(a[3]), "r"(b[0]), "r"(b[1]));
}

// Swizzled smem offset for (row, 16B-chunk), 128B rows, full 8-way XOR.
__device__ __forceinline__ uint32_t swz(int r, int c) {
    return (uint32_t)(r * 128 + ((c ^ (r & 7)) << 4));
}

// ---------------------------------------------------------------------------
// fp16 tensor-core GEMM:  C = alpha * A[M,K] * B[N,K]^T   (both K-major, NT)
// TRI:  packed lower-triangular tile grid.  CK: limit K to m0+128.
// OUT16: store C as fp16.  REV: heavy tiles first.  PSEL: z indexes table.
// ROPE: apply rotary rotation in the epilogue (z<2 only); requires B's
//       output features permuted so (d, d+256) pairs sit at (2d, 2d+1).
// CTA tile 128x128, K-chunk 64, 128 threads, 4 warps (2m x 2n), warp 64x64,
// 3-stage cp.async pipeline, one sync per chunk, 2 CTAs/SM.
// ---------------------------------------------------------------------------
#define NSTG   3
#define STG_B  32768                        // A 128*128B + B 128*128B
#define GEMM_SMEM (NSTG * STG_B)            // 98304 -> 2 CTAs/SM (192KB)

template <bool TRI, bool CK, bool OUT16, bool REV, bool PSEL, bool ROPE>
__global__ __launch_bounds__(128, 2) void gemm_fp16(
    GemmPtrs P, int Kdim, int lda, int ldb, int ldc,
    long long aO, long long aI, long long bO, long long bI, long long cO, long long cI,
    float alpha)
{
    int m0, n0;
    if (TRI) {
        int tt = blockIdx.x;
        int r = (int)((sqrtf(8.0f * (float)tt + 1.0f) - 1.0f) * 0.5f);
        if (r * (r + 1) / 2 > tt) r--;
        if ((r + 1) * (r + 2) / 2 <= tt) r++;
        m0 = r * 128;
        n0 = (tt - r * (r + 1) / 2) * 128;
    } else {
        const int my = REV ? (gridDim.y - 1 - blockIdx.y) : blockIdx.y;
        m0 = my * 128;
        n0 = blockIdx.x * 128;
    }

    const int z = blockIdx.z;
    const __half* A;
    const __half* B;
    if (PSEL) {
        A = P.A[z];
        B = P.B[z];
    } else {
        A = P.A[0] + (long long)(z >> 3) * aO + (long long)(z & 7) * aI;
        B = P.B[0] + (long long)(z >> 3) * bO + (long long)(z & 7) * bI;
    }

    const int kLim = CK ? ((Kdim < m0 + 128) ? Kdim : (m0 + 128)) : Kdim;
    const int nk = kLim >> 6;               // 64-wide K chunks

    extern __shared__ char smem[];
    const uint32_t sb = smem_u32(smem);
    const int tid = threadIdx.x, wid = tid >> 5, lane = tid & 31;
    const int wm = wid & 1, wn = wid >> 1;   // 2m x 2n warp grid

    const int ldr = tid >> 3;                // row group 0..15 (x8 -> 128 rows)
    const int ldc8 = tid & 7;                // 16B chunk 0..7 within 128B row
    auto load_stage = [&](int kt) {
        uint32_t stA = sb + (kt % NSTG) * STG_B;
        uint32_t stB = stA + 16384;
        const __half* Asrc = A + (size_t)m0 * lda + kt * 64;
        const __half* Bsrc = B + (size_t)n0 * ldb + kt * 64;
#pragma unroll
        for (int p = 0; p < 8; p++) {
            int r = ldr + p * 16;
            cpasync16(stA + swz(r, ldc8), Asrc + (size_t)r * lda + ldc8 * 8);
        }
#pragma unroll
        for (int p = 0; p < 8; p++) {
            int r = ldr + p * 16;
            cpasync16(stB + swz(r, ldc8), Bsrc + (size_t)r * ldb + ldc8 * 8);
        }
    };

#pragma unroll
    for (int s = 0; s < NSTG - 1; s++) { if (s < nk) load_stage(s); CP_COMMIT(); }

    float acc[4][8][4] = {};

    const int lrow = lane & 15;
    const int chHalf = lane >> 4;

    for (int kt = 0; kt < nk; kt++) {
        CP_WAIT1();
        __syncthreads();
        if (kt + NSTG - 1 < nk) load_stage(kt + NSTG - 1);
        CP_COMMIT();

        uint32_t stA = sb + (kt % NSTG) * STG_B;
        uint32_t stB = stA + 16384;
#pragma unroll
        for (int kk = 0; kk < 4; kk++) {
            const int ch = kk * 2 + chHalf;
            uint32_t a[4][4], b[8][2];
#pragma unroll
            for (int i = 0; i < 4; i++) {
                int r = wm * 64 + i * 16 + lrow;
                ldsm4(a[i][0], a[i][1], a[i][2], a[i][3], stA + swz(r, ch));
            }
#pragma unroll
            for (int jp = 0; jp < 4; jp++) {
                int r = wn * 64 + jp * 16 + lrow;
                uint32_t t0, t1, t2, t3;
                ldsm4(t0, t1, t2, t3, stB + swz(r, ch));
                b[jp * 2][0] = t0; b[jp * 2 + 1][0] = t1;
                b[jp * 2][1] = t2; b[jp * 2 + 1][1] = t3;
            }
#pragma unroll
            for (int i = 0; i < 4; i++)
#pragma unroll
                for (int j = 0; j < 8; j++) mma168(acc[i][j], a[i], b[j]);
        }
    }

    const int er = lane >> 2, ec = (lane & 3) * 2;
    if (OUT16) {
        __half* C = PSEL ? (__half*)P.C[z]
                  : (__half*)P.C[0] + (long long)(z >> 3) * cO + (long long)(z & 7) * cI;
        if (ROPE && z < 2) {
            // cols (c0, c0+1) form one rotation pair (x1, x2); freq = (c0%512)/2
#pragma unroll
            for (int i = 0; i < 4; i++) {
                int r0 = m0 + wm * 64 + i * 16 + er;
                int t0 = r0 & 2047, t1 = (r0 + 8) & 2047;
#pragma unroll
                for (int j = 0; j < 8; j++) {
                    int c0 = n0 + wn * 64 + j * 8 + ec;
                    int fd = (c0 & 511) >> 1;
                    float cc0 = g_cos[t0 * 256 + fd], ss0 = g_sin[t0 * 256 + fd];
                    float cc1 = g_cos[t1 * 256 + fd], ss1 = g_sin[t1 * 256 + fd];
                    float x1 = acc[i][j][0], x2 = acc[i][j][1];
                    __half2 h01 = __floats2half2_rn(x1 * cc0 - x2 * ss0,
                                                    x1 * ss0 + x2 * cc0);
                    x1 = acc[i][j][2]; x2 = acc[i][j][3];
                    __half2 h23 = __floats2half2_rn(x1 * cc1 - x2 * ss1,
                                                    x1 * ss1 + x2 * cc1);
                    *(__half2*)(C + (size_t)r0 * ldc + c0) = h01;
                    *(__half2*)(C + (size_t)(r0 + 8) * ldc + c0) = h23;
                }
            }
        } else {
#pragma unroll
            for (int i = 0; i < 4; i++) {
                int r0 = m0 + wm * 64 + i * 16 + er;
#pragma unroll
                for (int j = 0; j < 8; j++) {
                    int c0 = n0 + wn * 64 + j * 8 + ec;
                    __half2 h01 = __floats2half2_rn(acc[i][j][0] * alpha, acc[i][j][1] * alpha);
                    __half2 h23 = __floats2half2_rn(acc[i][j][2] * alpha, acc[i][j][3] * alpha);
                    *(__half2*)(C + (size_t)r0 * ldc + c0) = h01;
                    *(__half2*)(C + (size_t)(r0 + 8) * ldc + c0) = h23;
                }
            }
        }
    } else {
        float* C = PSEL ? (float*)P.C[z]
                 : (float*)P.C[0] + (long long)(z >> 3) * cO + (long long)(z & 7) * cI;
#pragma unroll
        for (int i = 0; i < 4; i++) {
            int r0 = m0 + wm * 64 + i * 16 + er;
#pragma unroll
            for (int j = 0; j < 8; j++) {
                int c0 = n0 + wn * 64 + j * 8 + ec;
                *(float2*)(C + (size_t)r0 * ldc + c0) =
                    make_float2(acc[i][j][0] * alpha, acc[i][j][1] * alpha);
                *(float2*)(C + (size_t)(r0 + 8) * ldc + c0) =
                    make_float2(acc[i][j][2] * alpha, acc[i][j][3] * alpha);
            }
        }
    }
}

// ---------------------------------------------------------------------------
// fused fp32 -> fp16 conversion for all 5 input tensors, 4 float4 per thread.
// Tensors 1,2 (Wq, Wk): output rows permuted so that rope pair (d, d+256) of
// each head lands at adjacent rows (2d, 2d+1) — rope becomes epilogue-local.
// ---------------------------------------------------------------------------
__global__ void f2h5(const float4* __restrict__ s0, const float4* __restrict__ s1,
                     const float4* __restrict__ s2, const float4* __restrict__ s3,
                     const float4* __restrict__ s4,
                     uint2* __restrict__ d0, uint2* __restrict__ d1,
                     uint2* __restrict__ d2, uint2* __restrict__ d3,
                     uint2* __restrict__ d4) {
    int which = blockIdx.x >> 10;            // 1024 blocks per tensor
    int base = (blockIdx.x & 1023) * 1024 + threadIdx.x;
    const float4* src = which == 0 ? s0 : which == 1 ? s1 : which == 2 ? s2
                      : which == 3 ? s3 : s4;
    uint2* dst = which == 0 ? d0 : which == 1 ? d1 : which == 2 ? d2
               : which == 3 ? d3 : d4;
    const bool perm = (which == 1) || (which == 2);
    float4 v[4];
#pragma unroll
    for (int p = 0; p < 4; p++) v[p] = src[base + p * 256];
#pragma unroll
    for (int p = 0; p < 4; p++) {
        __half2 a = __floats2half2_rn(v[p].x, v[p].y);
        __half2 b = __floats2half2_rn(v[p].z, v[p].w);
        int i = base + p * 256;
        int di = i;
        if (perm) {
            int r = i >> 8, c4 = i & 255;
            int h = r >> 9, dr = r & 511;
            int rp = h * 512 + ((dr < 256) ? (2 * dr) : (2 * (dr - 256) + 1));
            di = rp * 256 + c4;
        }
        dst[di] = make_uint2(*(uint32_t*)&a, *(uint32_t*)&b);
    }
}

// ---------------------------------------------------------------------------
// RoPE cos/sin table (fast-math-immune); consumed by the QKV GEMM epilogue.
// ---------------------------------------------------------------------------
__device__ __forceinline__ void sincos_cw(float a, float* sp, float* cp) {
    float j = rintf(a * 0.63661977236758138f);
    int   q = (int)j;
    float r = fmaf(j, -1.5707962512969971e+00f, a);
    r = fmaf(j, -7.5497894158615964e-08f, r);
    r = fmaf(j, -5.3903029534742385e-15f, r);
    float x2 = r * r;
    float s = r * (1.f + x2 * (-1.6666667e-1f + x2 * (8.3333333e-3f +
                    x2 * (-1.9841270e-4f + x2 * 2.7557319e-6f))));
    float c = 1.f + x2 * (-0.5f + x2 * (4.1666667e-2f +
                    x2 * (-1.3888889e-3f + x2 * 2.4801587e-5f)));
    switch (q & 3) {
        case 0: *sp =  s; *cp =  c; break;
        case 1: *sp =  c; *cp = -s; break;
        case 2: *sp = -s; *cp = -c; break;
        default:*sp = -c; *cp =  s; break;
    }
}

__global__ void rope_table() {
    int idx = blockIdx.x * 256 + threadIdx.x;
    int d = idx & 255, t = idx >> 8;
    float e = (float)d * (1.0f / 256.0f);
    const float LH = 13.287712097167969f;
    const float LL = 2.8238148e-7f;
    float p = -fmaf(e, LH, e * LL);
    float nf = floorf(p);
    float f  = p - nf;
    float y  = f * 0.69314718055994531f;
    float er = 1.f + y * (1.f + y * (0.5f + y * (0.16666667f + y * (0.041666667f +
               y * (0.0083333333f + y * (0.0013888889f + y * (1.9841270e-4f +
               y * (2.4801587e-5f + y * 2.7557319e-6f))))))));
    float invf = er * __int_as_float(((int)nf + 127) << 23);
    float ang = (float)t * invf;
    float s, c;
    sincos_cw(ang, &s, &c);
    g_cos[idx] = c;
    g_sin[idx] = s;
}

// ---------------------------------------------------------------------------
// Causal softmax on fp16 S. Two adjacent rows per 256-thread block
// (128 threads per row). Loads/stores only up to row's 128-pad boundary.
// Warp-shuffle reductions; 2 __syncthreads total.
// ---------------------------------------------------------------------------
__global__ void softmax_causal(__half2* __restrict__ S) {
    const int tid = threadIdx.x;
    const int grp = tid >> 7;                    // row group 0/1
    const int ltid = tid & 127;
    const int lane = tid & 31;
    const int wig = (tid >> 5) & 3;              // warp within group

    long long rr = (long long)blockIdx.x * 2 + grp;
    long long zz = rr >> 11;
    int i = (int)(rr & 2047);
    __half2* row = S + zz * (Tt * Tt / 2) + (size_t)i * (Tt / 2);
    const int L = i + 1;
    const int Lpad = (L + 127) & ~127;

    __shared__ float wredM[2][4], wredS[2][4];

    float v[16];
    float mx = -3.4e38f;
#pragma unroll
    for (int p = 0; p < 8; p++) {
        int j2 = ltid + p * 128;
        if (2 * j2 < Lpad) {
            float2 f = __half22float2(row[j2]);
            v[p * 2]     = (2 * j2     < L) ? f.x : -3.4e38f;
            v[p * 2 + 1] = (2 * j2 + 1 < L) ? f.y : -3.4e38f;
        } else {
            v[p * 2] = -3.4e38f; v[p * 2 + 1] = -3.4e38f;
        }
        mx = fmaxf(mx, fmaxf(v[p * 2], v[p * 2 + 1]));
    }
#pragma unroll
    for (int o = 16; o; o >>= 1) mx = fmaxf(mx, __shfl_xor_sync(0xffffffffu, mx, o));
    if (lane == 0) wredM[grp][wig] = mx;
    __syncthreads();
    mx = fmaxf(fmaxf(wredM[grp][0], wredM[grp][1]),
               fmaxf(wredM[grp][2], wredM[grp][3]));

    float sum = 0.f;
#pragma unroll
    for (int p = 0; p < 16; p++) {
        float e = (v[p] > -1e38f) ? expf(v[p] - mx) : 0.f;
        v[p] = e;
        sum += e;
    }
#pragma unroll
    for (int o = 16; o; o >>= 1) sum += __shfl_xor_sync(0xffffffffu, sum, o);
    if (lane == 0) wredS[grp][wig] = sum;
    __syncthreads();
    sum = (wredS[grp][0] + wredS[grp][1]) + (wredS[grp][2] + wredS[grp][3]);
    float inv = 1.0f / sum;

#pragma unroll
    for (int p = 0; p < 8; p++) {
        int j2 = ltid + p * 128;
        if (2 * j2 < Lpad)
            row[j2] = __floats2half2_rn(v[p * 2] * inv, v[p * 2 + 1] * inv);
    }
}

// ---------------------------------------------------------------------------
extern "C" void kernel_launch(void* const* d_in, const int* in_sizes, int n_in,
                              void* d_out, int out_size) {
    const float* x  = (const float*)d_in[0];
    const float* Wq = (const float*)d_in[1];
    const float* Wk = (const float*)d_in[2];
    const float* Wv = (const float*)d_in[3];
    const float* Wo = (const float*)d_in[4];
    float* out = (float*)d_out;

    __half *xh, *wqkh, *wvh, *woh, *qkh, *vTh, *attnh, *sh;
    cudaGetSymbolAddress((void**)&xh, g_xh);
    cudaGetSymbolAddress((void**)&wqkh, g_wqkh);
    cudaGetSymbolAddress((void**)&wvh, g_wvh);
    cudaGetSymbolAddress((void**)&woh, g_woh);
    cudaGetSymbolAddress((void**)&qkh, g_qkh);
    cudaGetSymbolAddress((void**)&vTh, g_vTh);
    cudaGetSymbolAddress((void**)&attnh, g_attnh);
    cudaGetSymbolAddress((void**)&sh, g_sh);

    cudaFuncSetAttribute(gemm_fp16<false, false, true, false, true, true>,
                         cudaFuncAttributeMaxDynamicSharedMemorySize, GEMM_SMEM);
    cudaFuncSetAttribute(gemm_fp16<false, false, true, false, true, true>,
                         cudaFuncAttributePreferredSharedMemoryCarveout, 100);
    cudaFuncSetAttribute(gemm_fp16<true, false, true, false, false, false>,
                         cudaFuncAttributeMaxDynamicSharedMemorySize, GEMM_SMEM);
    cudaFuncSetAttribute(gemm_fp16<true, false, true, false, false, false>,
                         cudaFuncAttributePreferredSharedMemoryCarveout, 100);
    cudaFuncSetAttribute(gemm_fp16<false, true, true, true, false, false>,
                         cudaFuncAttributeMaxDynamicSharedMemorySize, GEMM_SMEM);
    cudaFuncSetAttribute(gemm_fp16<false, true, true, true, false, false>,
                         cudaFuncAttributePreferredSharedMemoryCarveout, 100);
    cudaFuncSetAttribute(gemm_fp16<false, false, false, false, false, false>,
                         cudaFuncAttributeMaxDynamicSharedMemorySize, GEMM_SMEM);
    cudaFuncSetAttribute(gemm_fp16<false, false, false, false, false, false>,
                         cudaFuncAttributePreferredSharedMemoryCarveout, 100);

    dim3 blk(128);
    const long long TT  = (long long)Tt * Tt;
    const long long THD = (long long)Tt * HDc;
    const long long WSZ = (long long)HDc * Ee;     // one weight tensor
    const long long QSZ = (long long)Mc * HDc;     // one activation tensor

    // 0) rope table + fp32->fp16 conversion (Wq/Wk rows rope-pair permuted)
    rope_table<<<(Tt * Dh) / 256, 256>>>();
    f2h5<<<5 * 1024, 256>>>((const float4*)x, (const float4*)Wq, (const float4*)Wk,
                            (const float4*)Wv, (const float4*)Wo,
                            (uint2*)xh, (uint2*)wqkh, (uint2*)(wqkh + WSZ),
                            (uint2*)wvh, (uint2*)woh);

    // 1) Q, K, V projections in ONE launch; rope fused into epilogue for z<2
    {
        GemmPtrs P{};
        P.A[0] = xh;   P.B[0] = wqkh;        P.C[0] = qkh;
        P.A[1] = xh;   P.B[1] = wqkh + WSZ;  P.C[1] = qkh + QSZ;
        P.A[2] = wvh;  P.B[2] = xh;          P.C[2] = vTh;
        gemm_fp16<false, false, true, false, true, true><<<dim3(32, 32, 3), blk, GEMM_SMEM>>>(
            P, Ee, Ee, Ee, HDc, 0, 0, 0, 0, 0, 0, 1.f);
    }

    // 2) scores[b,h] = scale * q[b,h] @ k[b,h]^T  (packed triangular grid)
    {
        GemmPtrs P{};
        P.A[0] = qkh; P.B[0] = qkh + QSZ; P.C[0] = sh;
        gemm_fp16<true, false, true, false, false, false><<<dim3(136, 1, Bb * Hh), blk, GEMM_SMEM>>>(
            P, Dd, HDc, HDc, Tt,
            THD, (long long)Dd, THD, (long long)Dd,
            (long long)Hh * TT, TT, 0.044194173824159216f);
    }

    // 3) causal softmax (fp16 in/out, 2 rows per block, shfl reductions)
    softmax_causal<<<Bb * Hh * Tt / 2, 256>>>((__half2*)sh);

    // 4) attn[b,h] = P[b,h] @ vT[b,h]^T   (NT, causal K limit, heavy-first)
    {
        GemmPtrs P{};
        P.A[0] = sh; P.B[0] = vTh; P.C[0] = attnh;
        gemm_fp16<false, true, true, true, false, false><<<dim3(4, 16, Bb * Hh), blk, GEMM_SMEM>>>(
            P, Tt, Tt, Mc, HDc,
            (long long)Hh * TT, TT,
            (long long)Tt, (long long)Dd * Mc,
            (long long)Tt * HDc, (long long)Dd, 1.f);
    }

    // 5) out = attn_flat @ Wo^T  (fp32 output)
    {
        GemmPtrs P{};
        P.A[0] = attnh; P.B[0] = woh; P.C[0] = out;
        gemm_fp16<false, false, false, false, false, false><<<dim3(8, 32, 1), blk, GEMM_SMEM>>>(
            P, HDc, HDc, HDc, Ee, 0, 0, 0, 0, 0, 0, 1.f);
    }
}